// round 15
// baseline (speedup 1.0000x reference)
#include <cuda_runtime.h>
#include <cstdint>

// SepKANLayer1D: per-token KAN edge-spline layer.
// x: (4, 8, 65536) f32, w: (4, 640, 65536) f32, out: (4, 8, 65536) f32.
// Cooperative-tile streaming (R13) at 13 CTAs/SM:
//  - 16 coef rows staged per iteration via 16B cp.async.cg, double-buffered
//    (16 KB/CTA); uw/rw via direct __ldcs (4 regs).
//  - consume uses dynamic 4-of-8 gather: only bases m..m+3 are nonzero, and
//    smem row indexing is conflict-free for any m (row stride 128 = 0 mod 32).
// 4 threads/token (OH=2 via grid.y). Hardware scheduler balances the waves.

#define IN_C   8
#define OUT_C  8
#define NB     8
#define OH     2
#define NTOK   65536
#define WSIZE  640
#define NROWS  16               // coef rows staged per iteration
#define TPB    128

__device__ __forceinline__ void cp16(unsigned int smem_dst, const float* gptr) {
    asm volatile("cp.async.cg.shared.global [%0], [%1], 16;\n"
                 :: "r"(smem_dst), "l"(gptr));
}
__device__ __forceinline__ void cp_commit() {
    asm volatile("cp.async.commit_group;\n" ::: "memory");
}
template <int N>
__device__ __forceinline__ void cp_wait() {
    asm volatile("cp.async.wait_group %0;\n" :: "n"(N) : "memory");
}

__global__ __launch_bounds__(TPB, 13)   // reg cap 39 (R13 needed 37); 52 warps/SM
void sepkan_kernel(const float* __restrict__ x,
                   const float* __restrict__ w,
                   float* __restrict__ out) {
    __shared__ float buf[2][NROWS][TPB];     // 2 x 8 KB

    const int tid  = threadIdx.x;
    const int lane = tid & 31;
    const int wid  = tid >> 5;
    const int ob = blockIdx.y * OH;          // 0,2,4,6
    const int b  = blockIdx.x >> 9;          // 512 token-blocks per batch
    const int n0 = (blockIdx.x & 511) * TPB; // token base of this CTA
    const int n  = n0 + tid;

    const float* xp = x + (size_t)b * IN_C * NTOK + n;
    const float* wp = w + (size_t)b * WSIZE * NTOK + n;       // per-thread (uw/rw)
    const float* wbase = w + (size_t)b * WSIZE * NTOK + n0 + lane * 4;  // per-lane 16B chunk

    // stage one iteration's 16 coef rows into buffer s.
    // warp `wid` loads rows {wid, 4+wid, 8+wid, 12+wid}: one LDGSTS.16 per
    // lane covers a full 512B row per (warp, q).
    auto issue = [&](int i, int s) {
#pragma unroll
        for (int q = 0; q < 4; ++q) {
            const int r = 4 * q + wid;       // local coef row 0..15
            const int gr = i * OUT_C * NB + ob * NB + r;
            const unsigned int dst =
                (unsigned int)__cvta_generic_to_shared(&buf[s][r][lane * 4]);
            cp16(dst, wbase + (size_t)gr * NTOK);
        }
        cp_commit();
    };

    float acc0 = 0.0f, acc1 = 0.0f;
    float xi_next = __ldg(xp);               // prefetch channel 0's x

    issue(0, 0);                             // prologue

#pragma unroll 1
    for (int i = 0; i < IN_C; ++i) {
        const int s = i & 1;
        if (i + 1 < IN_C) issue(i + 1, s ^ 1);

        // uw/rw direct streaming loads for this iteration (batched early)
        const float* wu = wp + (size_t)(IN_C * OUT_C * NB + i * OUT_C + ob) * NTOK;
        const float* wr = wp + (size_t)(IN_C * OUT_C * NB + IN_C * OUT_C + i * OUT_C + ob) * NTOK;
        const float u0 = __ldcs(wu);
        const float u1 = __ldcs(wu + NTOK);
        const float r0 = __ldcs(wr);
        const float r1 = __ldcs(wr + NTOK);

        const float xi = xi_next;
        if (i + 1 < IN_C) xi_next = __ldg(xp + (i + 1) * NTOK);

        // ---- closed-form uniform cubic B-spline (load-independent shim) ----
        // m = clamp(floor(5x),0,4), u = 5x-m. Nonzero bases m..m+3:
        //   (1-u)^3/6, (3u^3-6u^2+4)/6, (-3u^3+3u^2+3u+1)/6, u^3/6
        int m = (int)(5.0f * xi);
        m = (m < 0) ? 0 : (m > 4 ? 4 : m);
        const float uu = 5.0f * xi - (float)m;
        const float vv = 1.0f - uu;
        const float uu2 = uu * uu, uu3 = uu2 * uu;
        float bw[4];
        bw[0] = vv * vv * vv * (1.0f / 6.0f);
        bw[1] = (3.0f * uu3 - 6.0f * uu2 + 4.0f) * (1.0f / 6.0f);
        bw[2] = (-3.0f * uu3 + 3.0f * uu2 + 3.0f * uu + 1.0f) * (1.0f / 6.0f);
        bw[3] = uu3 * (1.0f / 6.0f);

        const float sx = xi / (1.0f + __expf(-xi));   // silu

        // ---- wait for stage s (stage s+1 stays in flight), make visible ----
        if (i + 1 < IN_C) cp_wait<1>(); else cp_wait<0>();
        __syncthreads();

        // dynamic 4-of-8 gather: rows m..m+3 (o=ob) and 8+m..8+m+3 (o=ob+1).
        // address bank = tid%32 regardless of m -> conflict-free.
        const float* sv = &buf[s][0][tid];
        float sp0 = 0.0f, sp1 = 0.0f;
#pragma unroll
        for (int j = 0; j < 4; ++j) {
            sp0 = fmaf(bw[j], sv[(m + j) * TPB],      sp0);
            sp1 = fmaf(bw[j], sv[(NB + m + j) * TPB], sp1);
        }
        acc0 = fmaf(u0, sp0, acc0);
        acc1 = fmaf(u1, sp1, acc1);
        acc0 = fmaf(sx, r0, acc0);
        acc1 = fmaf(sx, r1, acc1);

        __syncthreads();                     // reads of s done before i+2 overwrites
    }

    float* yp = out + ((size_t)b * OUT_C + ob) * NTOK + n;
    __stcs(yp, acc0);
    __stcs(yp + NTOK, acc1);
}

extern "C" void kernel_launch(void* const* d_in, const int* in_sizes, int n_in,
                              void* d_out, int out_size) {
    const float* x = (const float*)d_in[0];   // (4, 8, 65536)
    const float* w = (const float*)d_in[1];   // (4, 640, 65536)
    float* out = (float*)d_out;               // (4, 8, 65536)

    const int total = 4 * NTOK;               // 262144 tokens
    dim3 grid(total / TPB, OUT_C / OH);       // (2048, 4)
    sepkan_kernel<<<grid, TPB>>>(x, w, out);
}

// round 16
// speedup vs baseline: 1.0039x; 1.0039x over previous
#include <cuda_runtime.h>
#include <cstdint>

// SepKANLayer1D: per-token KAN edge-spline layer.
// x: (4, 8, 65536) f32, w: (4, 640, 65536) f32, out: (4, 8, 65536) f32.
// Cooperative-tile streaming at 14 CTAs/SM (224 KB smem of 228 KB):
//  - 16 coef rows staged per iteration via 16B cp.async.cg, double-buffered,
//    committed as two 8-row half-groups (finer retirement, same semantics
//    via wait<2>); uw/rw via direct __ldcs (4 regs).
//  - consume uses dynamic 4-of-8 gather: only bases m..m+3 are nonzero, and
//    smem row indexing is conflict-free for any m (row stride 128 = 0 mod 32).
// 4 threads/token (OH=2 via grid.y).
// NOTE: measured HBM throughput (6.75 TB/s) is ~98% of the B300 LTS chip cap
// (~6300 B/cyc); traffic is irreducible, so this family is near-converged.

#define IN_C   8
#define OUT_C  8
#define NB     8
#define OH     2
#define NTOK   65536
#define WSIZE  640
#define NROWS  16               // coef rows staged per iteration
#define TPB    128

__device__ __forceinline__ void cp16(unsigned int smem_dst, const float* gptr) {
    asm volatile("cp.async.cg.shared.global [%0], [%1], 16;\n"
                 :: "r"(smem_dst), "l"(gptr));
}
__device__ __forceinline__ void cp_commit() {
    asm volatile("cp.async.commit_group;\n" ::: "memory");
}
template <int N>
__device__ __forceinline__ void cp_wait() {
    asm volatile("cp.async.wait_group %0;\n" :: "n"(N) : "memory");
}

__global__ __launch_bounds__(TPB, 14)   // 14 x 16 KB = 224 KB smem, reg cap 36 (uses 32)
void sepkan_kernel(const float* __restrict__ x,
                   const float* __restrict__ w,
                   float* __restrict__ out) {
    __shared__ float buf[2][NROWS][TPB];     // 2 x 8 KB

    const int tid  = threadIdx.x;
    const int lane = tid & 31;
    const int wid  = tid >> 5;
    const int ob = blockIdx.y * OH;          // 0,2,4,6
    const int b  = blockIdx.x >> 9;          // 512 token-blocks per batch
    const int n0 = (blockIdx.x & 511) * TPB; // token base of this CTA
    const int n  = n0 + tid;

    const float* xp = x + (size_t)b * IN_C * NTOK + n;
    const float* wp = w + (size_t)b * WSIZE * NTOK + n;       // per-thread (uw/rw)
    const float* wbase = w + (size_t)b * WSIZE * NTOK + n0 + lane * 4;  // per-lane 16B chunk

    // stage one iteration's 16 coef rows into buffer s as TWO 8-row commit
    // groups. warp `wid` loads rows {wid, 4+wid} then {8+wid, 12+wid}: one
    // LDGSTS.16 per lane covers a full 512B row per (warp, q).
    auto issue = [&](int i, int s) {
#pragma unroll
        for (int h = 0; h < 2; ++h) {
#pragma unroll
            for (int q = 0; q < 2; ++q) {
                const int r = 8 * h + 4 * q + wid;   // local coef row 0..15
                const int gr = i * OUT_C * NB + ob * NB + r;
                const unsigned int dst =
                    (unsigned int)__cvta_generic_to_shared(&buf[s][r][lane * 4]);
                cp16(dst, wbase + (size_t)gr * NTOK);
            }
            cp_commit();
        }
    };

    float acc0 = 0.0f, acc1 = 0.0f;
    float xi_next = __ldg(xp);               // prefetch channel 0's x

    issue(0, 0);                             // prologue (2 groups)

#pragma unroll 1
    for (int i = 0; i < IN_C; ++i) {
        const int s = i & 1;
        if (i + 1 < IN_C) issue(i + 1, s ^ 1);   // +2 groups (max 4 outstanding)

        // uw/rw direct streaming loads for this iteration (batched early)
        const float* wu = wp + (size_t)(IN_C * OUT_C * NB + i * OUT_C + ob) * NTOK;
        const float* wr = wp + (size_t)(IN_C * OUT_C * NB + IN_C * OUT_C + i * OUT_C + ob) * NTOK;
        const float u0 = __ldcs(wu);
        const float u1 = __ldcs(wu + NTOK);
        const float r0 = __ldcs(wr);
        const float r1 = __ldcs(wr + NTOK);

        const float xi = xi_next;
        if (i + 1 < IN_C) xi_next = __ldg(xp + (i + 1) * NTOK);

        // ---- closed-form uniform cubic B-spline (load-independent shim) ----
        // m = clamp(floor(5x),0,4), u = 5x-m. Nonzero bases m..m+3:
        //   (1-u)^3/6, (3u^3-6u^2+4)/6, (-3u^3+3u^2+3u+1)/6, u^3/6
        int m = (int)(5.0f * xi);
        m = (m < 0) ? 0 : (m > 4 ? 4 : m);
        const float uu = 5.0f * xi - (float)m;
        const float vv = 1.0f - uu;
        const float uu2 = uu * uu, uu3 = uu2 * uu;
        float bw[4];
        bw[0] = vv * vv * vv * (1.0f / 6.0f);
        bw[1] = (3.0f * uu3 - 6.0f * uu2 + 4.0f) * (1.0f / 6.0f);
        bw[2] = (-3.0f * uu3 + 3.0f * uu2 + 3.0f * uu + 1.0f) * (1.0f / 6.0f);
        bw[3] = uu3 * (1.0f / 6.0f);

        const float sx = xi / (1.0f + __expf(-xi));   // silu

        // ---- wait for stage s (both its half-groups), stage s+1 in flight ----
        if (i + 1 < IN_C) cp_wait<2>(); else cp_wait<0>();
        __syncthreads();

        // dynamic 4-of-8 gather: rows m..m+3 (o=ob) and 8+m..8+m+3 (o=ob+1).
        // address bank = tid%32 regardless of m -> conflict-free.
        const float* sv = &buf[s][0][tid];
        float sp0 = 0.0f, sp1 = 0.0f;
#pragma unroll
        for (int j = 0; j < 4; ++j) {
            sp0 = fmaf(bw[j], sv[(m + j) * TPB],      sp0);
            sp1 = fmaf(bw[j], sv[(NB + m + j) * TPB], sp1);
        }
        acc0 = fmaf(u0, sp0, acc0);
        acc1 = fmaf(u1, sp1, acc1);
        acc0 = fmaf(sx, r0, acc0);
        acc1 = fmaf(sx, r1, acc1);

        __syncthreads();                     // reads of s done before i+2 overwrites
    }

    float* yp = out + ((size_t)b * OUT_C + ob) * NTOK + n;
    __stcs(yp, acc0);
    __stcs(yp + NTOK, acc1);
}

extern "C" void kernel_launch(void* const* d_in, const int* in_sizes, int n_in,
                              void* d_out, int out_size) {
    const float* x = (const float*)d_in[0];   // (4, 8, 65536)
    const float* w = (const float*)d_in[1];   // (4, 640, 65536)
    float* out = (float*)d_out;               // (4, 8, 65536)

    const int total = 4 * NTOK;               // 262144 tokens
    dim3 grid(total / TPB, OUT_C / OH);       // (2048, 4)
    sepkan_kernel<<<grid, TPB>>>(x, w, out);
}